// round 7
// baseline (speedup 1.0000x reference)
#include <cuda_runtime.h>
#include <cuda_bf16.h>

#define NB 32
#define NP 32768
#define NC 81
#define NANCH (NB * NP)
#define TPB 128
#define WARPS 4
#define ROWS 8                           // rows per tile (per warp)
#define NBUF 3
#define WTILES 32                        // tiles per warp -> 256 anchors/warp
#define APB (WARPS * ROWS * WTILES)      // 1024 anchors per block
#define GRID (NANCH / APB)               // 1024 blocks, 32 per batch
#define TILE_FLOATS (ROWS * NC)          // 648
#define TILE_BYTES (TILE_FLOATS * 4)     // 2592
#define TILE_F4 (TILE_FLOATS / 4)        // 162
#define WARP_SMEM (NBUF * TILE_FLOATS)   // 1944 floats per warp
#define NWSLOT (GRID * WARPS)            // 4096 per-warp partial slots
#define CBLK 16                          // collect blocks per batch
#define CGRID (NB * CBLK)                // 512

// -------- scratch (device globals; zero-initialized at module load) --------
__device__ float  g_lossc[NANCH];         // mining scores (0 for pos/ignored)
__device__ float  g_cand[NANCH];          // per-batch candidate values (boundary bin)
__device__ double g_part_lossl[NWSLOT];   // per-warp smooth-L1 partials (plain ST)
__device__ double g_part_cepos[NWSLOT];   // per-warp CE-over-positives partials
__device__ int    g_numpos[NB];           // per-batch positive counts
__device__ int    g_hist12[NB * 4096];    // per-batch 12-bit (bits[31:20]) histogram
__device__ int    g_mdone[NB];            // per-batch main-block completion counters
__device__ int    g_k[NB], g_krem[NB], g_bin12[NB];
__device__ int    g_candcnt[NB];
__device__ double g_sumHi[NB];            // per-batch sum of values with digit > bin12
__device__ double g_conf_neg;             // CE sum over mined negatives
__device__ unsigned g_done;               // resolve completion counter

__device__ __forceinline__ unsigned smem_u32(const void* p) {
    return (unsigned)__cvta_generic_to_shared(p);
}
__device__ __forceinline__ void cp16(unsigned dst, const void* src) {
    asm volatile("cp.async.ca.shared.global [%0], [%1], 16;\n" :: "r"(dst), "l"(src));
}
#define CP_COMMIT() asm volatile("cp.async.commit_group;\n" ::: "memory")
#define CP_WAIT1()  asm volatile("cp.async.wait_group 1;\n" ::: "memory")

// ============ main: per-warp cp.async pipelines; last block per batch finds bin12 ============
__global__ void __launch_bounds__(TPB, 7) mb_main_kernel(
    const float* __restrict__ loc_t, const float* __restrict__ loc_data,
    const int* __restrict__ conf_t, const float* __restrict__ conf_data)
{
    __shared__ float smem[WARPS * WARP_SMEM];   // 31104 B
    __shared__ int gs[TPB];
    __shared__ int s_isLast;

    const int tid  = threadIdx.x;
    const int w    = tid >> 5;
    const int lane = tid & 31;
    const int q    = lane & 3;               // quarter-row worker
    const int row  = lane >> 2;              // 0..7
    const int b    = blockIdx.x >> 5;        // batch (32 blocks per batch)
    const size_t wbase = (size_t)blockIdx.x * APB + (size_t)w * (ROWS * WTILES);
    float* const wsm = smem + w * WARP_SMEM;
    const unsigned sbase = smem_u32(wsm);
    const int hbase = b << 12;

    auto stage = [&](int t, int buf) {
        const float4* __restrict__ src =
            (const float4*)(conf_data) + (((size_t)(wbase + (size_t)t * ROWS) * NC) >> 2);
        const unsigned dst = sbase + (unsigned)buf * TILE_BYTES;
        #pragma unroll
        for (int j = 0; j < 5; j++)
            cp16(dst + (unsigned)(lane + j * 32) * 16u, src + lane + j * 32);
        if (lane < TILE_F4 - 160)
            cp16(dst + (unsigned)(lane + 160) * 16u, src + lane + 160);
    };

    stage(0, 0); CP_COMMIT();
    stage(1, 1); CP_COMMIT();

    float ll = 0.f, ce = 0.f;
    int   np = 0;
    int   cbuf = 0, sbuf = 2;

    for (int t = 0; t < WTILES; t++) {
        CP_WAIT1();
        __syncwarp();
        if (t + 2 < WTILES) stage(t + 2, sbuf);
        CP_COMMIT();
        sbuf = (sbuf == NBUF - 1) ? 0 : sbuf + 1;

        const float* __restrict__ r = wsm + cbuf * TILE_FLOATS + row * NC;
        cbuf = (cbuf == NBUF - 1) ? 0 : cbuf + 1;

        float s0 = 0.f, s1 = 0.f, s2 = 0.f, s3 = 0.f;
        #pragma unroll
        for (int i = 0; i < 20; i += 4) {
            s0 += __expf(r[q * 20 + i]);
            s1 += __expf(r[q * 20 + i + 1]);
            s2 += __expf(r[q * 20 + i + 2]);
            s3 += __expf(r[q * 20 + i + 3]);
        }
        float s = (s0 + s1) + (s2 + s3);
        if (q == 3) s += __expf(r[80]);
        s += __shfl_xor_sync(0xffffffffu, s, 1);
        s += __shfl_xor_sync(0xffffffffu, s, 2);

        if (q == 0) {
            const size_t anchor = wbase + (size_t)t * ROWS + row;
            const int traw = __ldg(&conf_t[anchor]);
            const int tgt  = traw < 0 ? 0 : traw;
            const float val = __logf(s) - r[tgt];          // cross-entropy

            const float stv = (traw == 0) ? fmaxf(val, 0.f) : 0.f;
            g_lossc[anchor] = stv;

            // fused radix digit 1: 12-bit histogram (8 active lanes, warp-aggregated)
            const unsigned bin = __float_as_uint(stv) >> 20;
            const unsigned peers = __match_any_sync(0x11111111u, bin);
            if (lane == __ffs(peers) - 1)
                atomicAdd(&g_hist12[hbase + (int)bin], __popc(peers));

            if (traw > 0) {
                float4 a = ((const float4*)loc_data)[anchor];
                float4 bb = ((const float4*)loc_t)[anchor];
                float d0 = fabsf(a.x - bb.x), d1 = fabsf(a.y - bb.y);
                float d2 = fabsf(a.z - bb.z), d3 = fabsf(a.w - bb.w);
                float sl1;
                sl1  = (d0 < 1.f) ? 0.5f * d0 * d0 : d0 - 0.5f;
                sl1 += (d1 < 1.f) ? 0.5f * d1 * d1 : d1 - 0.5f;
                sl1 += (d2 < 1.f) ? 0.5f * d2 * d2 : d2 - 0.5f;
                sl1 += (d3 < 1.f) ? 0.5f * d3 * d3 : d3 - 0.5f;
                ll += sl1; ce += val; np++;
            }
        }
    }

    #pragma unroll
    for (int o = 16; o; o >>= 1) {
        ll += __shfl_xor_sync(0xffffffffu, ll, o);
        ce += __shfl_xor_sync(0xffffffffu, ce, o);
        np += __shfl_xor_sync(0xffffffffu, np, o);
    }
    if (lane == 0) {
        const int slot = blockIdx.x * WARPS + w;
        g_part_lossl[slot] = (double)ll;
        g_part_cepos[slot] = (double)ce;
        if (np) atomicAdd(&g_numpos[b], np);
    }

    // ---- per-batch epilogue: last of the batch's 32 blocks finds bin12/krem ----
    __threadfence();
    if (tid == 0) s_isLast = (atomicAdd(&g_mdone[b], 1) == 31);
    __syncthreads();
    if (!s_isLast) return;
    __threadfence();

    const int* __restrict__ hb = g_hist12 + hbase;
    int acc = 0;
    #pragma unroll
    for (int j = 0; j < 32; j++) acc += hb[tid * 32 + j];
    gs[tid] = acc;
    __syncthreads();
    if (tid == 0) {
        const int npos = g_numpos[b];
        const int k = min(3 * npos, NP - 1);
        int bin12 = -1, krem = k;
        if (k > 0) {
            int g = 127;
            for (;;) { const int c = gs[g]; if (c >= krem) break; krem -= c; g--; }
            int j = 31;
            for (;;) { const int c = hb[g * 32 + j]; if (c >= krem) break; krem -= c; j--; }
            bin12 = g * 32 + j;
        }
        g_k[b] = k; g_krem[b] = krem; g_bin12[b] = bin12;
    }
}

// ============ collect: 16 blocks/batch; sumHi + boundary-bin candidate append ============
__global__ void __launch_bounds__(256) mb_collect_kernel() {
    const int b     = blockIdx.x >> 4;
    const int slice = blockIdx.x & 15;
    const int tid = threadIdx.x, lane = tid & 31, wid = tid >> 5;

    if (g_k[b] <= 0) return;
    const unsigned bin12 = (unsigned)g_bin12[b];
    const unsigned* __restrict__ uv =
        (const unsigned*)g_lossc + (size_t)b * NP + slice * 2048;

    unsigned u[8];
    #pragma unroll
    for (int j = 0; j < 8; j++) u[j] = __ldg(&uv[tid + j * 256]);

    float sHi = 0.f;
    #pragma unroll
    for (int j = 0; j < 8; j++)
        if ((u[j] >> 20) > bin12) sHi += __uint_as_float(u[j]);

    // ballot-aggregated candidate append
    #pragma unroll
    for (int j = 0; j < 8; j++) {
        const bool m = (u[j] >> 20) == bin12;
        const unsigned mk = __ballot_sync(0xffffffffu, m);
        if (mk) {
            const int ldr = __ffs(mk) - 1;
            int base = 0;
            if (lane == ldr) base = atomicAdd(&g_candcnt[b], __popc(mk));
            base = __shfl_sync(0xffffffffu, base, ldr);
            if (m) g_cand[(size_t)b * NP + base + __popc(mk & ((1u << lane) - 1))] =
                       __uint_as_float(u[j]);
        }
    }

    // block-reduce sumHi -> one double atomic per block
    #pragma unroll
    for (int o = 16; o; o >>= 1) sHi += __shfl_xor_sync(0xffffffffu, sHi, o);
    __shared__ float ws[8];
    if (lane == 0) ws[wid] = sHi;
    __syncthreads();
    if (tid == 0) {
        float t = 0.f;
        #pragma unroll
        for (int i = 0; i < 8; i++) t += ws[i];
        atomicAdd(&g_sumHi[b], (double)t);
    }
}

// ============ resolve: radix over candidates only; last block finalizes+resets ============
__global__ void __launch_bounds__(1024) mb_resolve_kernel(float* __restrict__ out) {
    const int b = blockIdx.x;
    const int tid = threadIdx.x, lane = tid & 31, wid = tid >> 5;

    __shared__ int   hist[4096];
    __shared__ float fsum[4096];
    __shared__ int   gsum[128];
    __shared__ int   s_binA, s_binB, s_krem2, s_krem3;

    const int k = g_k[b];
    if (k > 0) {
        const int krem = g_krem[b];
        const int ncand = g_candcnt[b];
        const float* __restrict__ cv = g_cand + (size_t)b * NP;

        for (int i = tid; i < 4096; i += 1024) { hist[i] = 0; fsum[i] = 0.f; }
        __syncthreads();

        // pass 1: bits[19:8] over candidates
        for (int i = tid; i < ncand; i += 1024) {
            const unsigned u = __float_as_uint(cv[i]);
            const int bb = (u >> 8) & 4095;
            atomicAdd(&hist[bb], 1);
            atomicAdd(&fsum[bb], __uint_as_float(u));
        }
        __syncthreads();

        // find binA (two-level suffix scan)
        #pragma unroll
        for (int gg = 0; gg < 4; gg++) {
            const int g = wid * 4 + gg;
            int v = hist[g * 32 + lane];
            #pragma unroll
            for (int o = 16; o; o >>= 1) v += __shfl_xor_sync(0xffffffffu, v, o);
            if (lane == 0) gsum[g] = v;
        }
        __syncthreads();
        if (tid == 0) {
            int kr = krem, g = 127;
            for (;;) { if (gsum[g] >= kr) break; kr -= gsum[g]; g--; }
            int j = 31;
            for (;;) { const int c = hist[g * 32 + j]; if (c >= kr) break; kr -= c; j--; }
            s_binA = g * 32 + j; s_krem2 = kr;
        }
        __syncthreads();
        const int binA = s_binA;

        // suffix cnt/sum over bins > binA
        int cA = 0; float sA = 0.f;
        for (int i = tid; i < 4096; i += 1024)
            if (i > binA) { cA += hist[i]; sA += fsum[i]; }
        #pragma unroll
        for (int o = 16; o; o >>= 1) {
            cA += __shfl_xor_sync(0xffffffffu, cA, o);
            sA += __shfl_xor_sync(0xffffffffu, sA, o);
        }
        __shared__ int wc[32]; __shared__ float wsf[32];
        if (lane == 0) { wc[wid] = cA; wsf[wid] = sA; }

        // zero 256 bins for pass 2
        if (tid >= 512 && tid < 768) { hist[tid - 512] = 0; fsum[tid - 512] = 0.f; }
        __syncthreads();
        int cntA = 0; float sumA = 0.f;
        #pragma unroll
        for (int i = 0; i < 32; i++) { cntA += wc[i]; sumA += wsf[i]; }

        // pass 2: bits[7:0] for mid == binA
        for (int i = tid; i < ncand; i += 1024) {
            const unsigned u = __float_as_uint(cv[i]);
            if ((int)((u >> 8) & 4095) == binA) {
                atomicAdd(&hist[u & 255], 1);
                atomicAdd(&fsum[u & 255], __uint_as_float(u));
            }
        }
        __syncthreads();

        // find binB (256 bins)
        if (wid < 8) {
            int v = hist[wid * 32 + lane];
            #pragma unroll
            for (int o = 16; o; o >>= 1) v += __shfl_xor_sync(0xffffffffu, v, o);
            if (lane == 0) gsum[wid] = v;
        }
        __syncthreads();
        if (tid == 0) {
            int kr = s_krem2, g = 7;
            for (;;) { if (gsum[g] >= kr) break; kr -= gsum[g]; g--; }
            int j = 31;
            for (;;) { const int c = hist[g * 32 + j]; if (c >= kr) break; kr -= c; j--; }
            s_binB = g * 32 + j; s_krem3 = kr;
        }
        __syncthreads();
        const int binB = s_binB;

        int cB = 0; float sB = 0.f;
        if (tid < 256 && tid > binB) { cB = hist[tid]; sB = fsum[tid]; }
        #pragma unroll
        for (int o = 16; o; o >>= 1) {
            cB += __shfl_xor_sync(0xffffffffu, cB, o);
            sB += __shfl_xor_sync(0xffffffffu, sB, o);
        }
        if (lane == 0) { wc[wid] = cB; wsf[wid] = sB; }
        __syncthreads();

        if (tid == 0) {
            int cntB = 0; float sumB = 0.f;
            #pragma unroll
            for (int i = 0; i < 8; i++) { cntB += wc[i]; sumB += wsf[i]; }
            const unsigned T = ((unsigned)g_bin12[b] << 20) | ((unsigned)binA << 8) | (unsigned)binB;
            const double Tf = (double)__uint_as_float(T);
            const int    cntTot = (k - krem) + cntA + cntB;
            const double sumTot = g_sumHi[b] + (double)sumA + (double)sumB;
            atomicAdd(&g_conf_neg, sumTot + (double)(k - cntTot) * Tf);
        }
        __syncthreads();
    }

    // per-batch reset for next graph replay (not read after this point)
    {
        int* hb = g_hist12 + (b << 12);
        for (int i = tid; i < 4096; i += 1024) hb[i] = 0;
        if (tid == 0) { g_candcnt[b] = 0; g_mdone[b] = 0; g_sumHi[b] = 0.0; }
    }

    // ---- last-block finalize + global reset ----
    __shared__ int s_last;
    if (tid == 0) {
        __threadfence();
        s_last = (atomicAdd(&g_done, 1u) == (unsigned)(NB - 1)) ? 1 : 0;
    }
    __syncthreads();
    if (!s_last) return;
    __threadfence();

    __shared__ double fll[32], fce[32];
    double a = 0.0, c = 0.0;
    #pragma unroll
    for (int j = 0; j < NWSLOT / 1024; j++) {
        a += g_part_lossl[tid + j * 1024];
        c += g_part_cepos[tid + j * 1024];
    }
    #pragma unroll
    for (int o = 16; o; o >>= 1) {
        a += __shfl_xor_sync(0xffffffffu, a, o);
        c += __shfl_xor_sync(0xffffffffu, c, o);
    }
    if (lane == 0) { fll[wid] = a; fce[wid] = c; }
    __syncthreads();
    if (tid == 0) {
        double ll = 0.0, ce = 0.0;
        #pragma unroll
        for (int i = 0; i < 32; i++) { ll += fll[i]; ce += fce[i]; }
        int N = 0;
        for (int i = 0; i < NB; i++) N += g_numpos[i];
        const double Nd = (double)N;
        out[0] = (float)(ll / Nd);
        out[1] = (float)((ce + g_conf_neg) / Nd);
        g_conf_neg = 0.0; g_done = 0u;
    }
    if (tid < NB) g_numpos[tid] = 0;
}

extern "C" void kernel_launch(void* const* d_in, const int* in_sizes, int n_in,
                              void* d_out, int out_size) {
    const float* loc_t = nullptr;
    const float* loc_data = nullptr;
    const int*   conf_t = nullptr;
    const float* conf_data = nullptr;
    for (int i = 0; i < n_in; i++) {
        if (in_sizes[i] == NANCH * NC)      conf_data = (const float*)d_in[i];
        else if (in_sizes[i] == NANCH)      conf_t    = (const int*)d_in[i];
        else if (in_sizes[i] == NANCH * 4) {
            if (!loc_t) loc_t = (const float*)d_in[i];
            else        loc_data = (const float*)d_in[i];
        }
    }

    static bool attr_set = false;
    if (!attr_set) {
        cudaFuncSetAttribute(mb_main_kernel,
                             cudaFuncAttributePreferredSharedMemoryCarveout, 100);
        attr_set = true;
    }

    mb_main_kernel<<<GRID, TPB>>>(loc_t, loc_data, conf_t, conf_data);
    mb_collect_kernel<<<CGRID, 256>>>();
    mb_resolve_kernel<<<NB, 1024>>>((float*)d_out);
}

// round 8
// speedup vs baseline: 1.0912x; 1.0912x over previous
#include <cuda_runtime.h>
#include <cuda_bf16.h>

#define NB 32
#define NP 32768
#define NC 81
#define NANCH (NB * NP)
#define TPB 128
#define WARPS 4
#define ROWS 8                           // rows per tile (per warp)
#define NBUF 3
#define WTILES 32                        // tiles per warp -> 256 anchors/warp
#define APB (WARPS * ROWS * WTILES)      // 1024 anchors per block
#define GRID (NANCH / APB)               // 1024 blocks, 32 per batch
#define TILE_FLOATS (ROWS * NC)          // 648
#define TILE_BYTES (TILE_FLOATS * 4)     // 2592
#define TILE_F4 (TILE_FLOATS / 4)        // 162
#define WARP_SMEM (NBUF * TILE_FLOATS)   // 1944 floats per warp
#define NWSLOT (GRID * WARPS)            // 4096 per-warp partial slots
#define PBLK 8                           // post blocks per batch
#define PGRID (NB * PBLK)                // 256
#define PTPB 256

// -------- scratch (device globals; zero-initialized at module load) --------
__device__ float  g_lossc[NANCH];         // mining scores (0 for pos/ignored)
__device__ float  g_cand[NANCH];          // per-batch boundary-bin candidates
__device__ double g_part_lossl[NWSLOT];   // per-warp smooth-L1 partials (plain ST)
__device__ double g_part_cepos[NWSLOT];   // per-warp CE-over-positives partials
__device__ int    g_numpos[NB];           // per-batch positive counts
__device__ int    g_hist12[NB * 4096];    // per-batch 12-bit (bits[31:20]) histogram
__device__ int    g_candcnt[NB];
__device__ int    g_pdone[NB];            // per-batch post-block completion counters
__device__ double g_sumHi[NB];            // per-batch sum of values with digit > bin12
__device__ double g_conf_neg;             // CE sum over mined negatives
__device__ unsigned g_done;               // global completion counter

__device__ __forceinline__ unsigned smem_u32(const void* p) {
    return (unsigned)__cvta_generic_to_shared(p);
}
__device__ __forceinline__ void cp16(unsigned dst, const void* src) {
    asm volatile("cp.async.ca.shared.global [%0], [%1], 16;\n" :: "r"(dst), "l"(src));
}
#define CP_COMMIT() asm volatile("cp.async.commit_group;\n" ::: "memory")
#define CP_WAIT1()  asm volatile("cp.async.wait_group 1;\n" ::: "memory")

// ============ main: per-warp cp.async pipelines (lean; R6 shape) ============
__global__ void __launch_bounds__(TPB, 7) mb_main_kernel(
    const float* __restrict__ loc_t, const float* __restrict__ loc_data,
    const int* __restrict__ conf_t, const float* __restrict__ conf_data)
{
    __shared__ float smem[WARPS * WARP_SMEM];   // 31104 B

    const int tid  = threadIdx.x;
    const int w    = tid >> 5;
    const int lane = tid & 31;
    const int q    = lane & 3;               // quarter-row worker
    const int row  = lane >> 2;              // 0..7
    const size_t wbase = (size_t)blockIdx.x * APB + (size_t)w * (ROWS * WTILES);
    float* const wsm = smem + w * WARP_SMEM;
    const unsigned sbase = smem_u32(wsm);
    const int hbase = (blockIdx.x >> 5) << 12;   // batch * 4096

    auto stage = [&](int t, int buf) {
        const float4* __restrict__ src =
            (const float4*)(conf_data) + (((size_t)(wbase + (size_t)t * ROWS) * NC) >> 2);
        const unsigned dst = sbase + (unsigned)buf * TILE_BYTES;
        #pragma unroll
        for (int j = 0; j < 5; j++)
            cp16(dst + (unsigned)(lane + j * 32) * 16u, src + lane + j * 32);
        if (lane < TILE_F4 - 160)
            cp16(dst + (unsigned)(lane + 160) * 16u, src + lane + 160);
    };

    stage(0, 0); CP_COMMIT();
    stage(1, 1); CP_COMMIT();

    float ll = 0.f, ce = 0.f;
    int   np = 0;
    int   cbuf = 0, sbuf = 2;

    for (int t = 0; t < WTILES; t++) {
        CP_WAIT1();
        __syncwarp();
        if (t + 2 < WTILES) stage(t + 2, sbuf);
        CP_COMMIT();
        sbuf = (sbuf == NBUF - 1) ? 0 : sbuf + 1;

        const float* __restrict__ r = wsm + cbuf * TILE_FLOATS + row * NC;
        cbuf = (cbuf == NBUF - 1) ? 0 : cbuf + 1;

        float s0 = 0.f, s1 = 0.f, s2 = 0.f, s3 = 0.f;
        #pragma unroll
        for (int i = 0; i < 20; i += 4) {
            s0 += __expf(r[q * 20 + i]);
            s1 += __expf(r[q * 20 + i + 1]);
            s2 += __expf(r[q * 20 + i + 2]);
            s3 += __expf(r[q * 20 + i + 3]);
        }
        float s = (s0 + s1) + (s2 + s3);
        if (q == 3) s += __expf(r[80]);
        s += __shfl_xor_sync(0xffffffffu, s, 1);
        s += __shfl_xor_sync(0xffffffffu, s, 2);

        if (q == 0) {
            const size_t anchor = wbase + (size_t)t * ROWS + row;
            const int traw = __ldg(&conf_t[anchor]);
            const int tgt  = traw < 0 ? 0 : traw;
            const float val = __logf(s) - r[tgt];          // cross-entropy

            const float stv = (traw == 0) ? fmaxf(val, 0.f) : 0.f;
            g_lossc[anchor] = stv;

            // fused radix digit 1: 12-bit histogram (8 active lanes, warp-aggregated)
            const unsigned bin = __float_as_uint(stv) >> 20;
            const unsigned peers = __match_any_sync(0x11111111u, bin);
            if (lane == __ffs(peers) - 1)
                atomicAdd(&g_hist12[hbase + (int)bin], __popc(peers));

            if (traw > 0) {
                float4 a = ((const float4*)loc_data)[anchor];
                float4 bb = ((const float4*)loc_t)[anchor];
                float d0 = fabsf(a.x - bb.x), d1 = fabsf(a.y - bb.y);
                float d2 = fabsf(a.z - bb.z), d3 = fabsf(a.w - bb.w);
                float sl1;
                sl1  = (d0 < 1.f) ? 0.5f * d0 * d0 : d0 - 0.5f;
                sl1 += (d1 < 1.f) ? 0.5f * d1 * d1 : d1 - 0.5f;
                sl1 += (d2 < 1.f) ? 0.5f * d2 * d2 : d2 - 0.5f;
                sl1 += (d3 < 1.f) ? 0.5f * d3 * d3 : d3 - 0.5f;
                ll += sl1; ce += val; np++;
            }
        }
    }

    #pragma unroll
    for (int o = 16; o; o >>= 1) {
        ll += __shfl_xor_sync(0xffffffffu, ll, o);
        ce += __shfl_xor_sync(0xffffffffu, ce, o);
        np += __shfl_xor_sync(0xffffffffu, np, o);
    }
    if (lane == 0) {
        const int slot = blockIdx.x * WARPS + w;
        g_part_lossl[slot] = (double)ll;
        g_part_cepos[slot] = (double)ce;
        if (np) atomicAdd(&g_numpos[blockIdx.x >> 5], np);
    }
}

// ============ post: redundant bin12-find + slice scan; per-batch last resolves ============
__global__ void __launch_bounds__(PTPB) mb_post_kernel(float* __restrict__ out) {
    const int b     = blockIdx.x >> 3;
    const int slice = blockIdx.x & (PBLK - 1);
    const int tid = threadIdx.x, lane = tid & 31, wid = tid >> 5;

    __shared__ int   hist[4096];
    __shared__ float fsum[4096];
    __shared__ int   ts[PTPB];
    __shared__ int   s_bin12, s_krem, s_binA, s_binB, s_krem2;

    const int np = g_numpos[b];
    const int k  = min(3 * np, NP - 1);

    if (k > 0) {
        // ---- every block redundantly finds bin12 from L2-resident hist12 ----
        const int* __restrict__ gh = g_hist12 + (b << 12);
        int part = 0;
        #pragma unroll
        for (int j = 0; j < 16; j++) {
            const int v = __ldg(&gh[tid * 16 + j]);
            hist[tid * 16 + j] = v;
            part += v;
        }
        ts[tid] = part;
        __syncthreads();
        if (tid == 0) {
            int krem = k, g = PTPB - 1;
            for (;;) { const int c = ts[g]; if (c >= krem) break; krem -= c; g--; }
            int j = 15;
            for (;;) { const int c = hist[g * 16 + j]; if (c >= krem) break; krem -= c; j--; }
            s_bin12 = g * 16 + j; s_krem = krem;
        }
        __syncthreads();
        const unsigned bin12 = (unsigned)s_bin12;

        // ---- scan this block's NP/8 slice: sumHi + boundary candidates ----
        const uint4* __restrict__ uv = (const uint4*)
            ((const unsigned*)g_lossc + (size_t)b * NP + slice * (NP / PBLK));
        float sHi = 0.f;
        #pragma unroll
        for (int j = 0; j < 4; j++) {
            const uint4 u4 = __ldg(&uv[tid + j * PTPB]);
            const unsigned uu[4] = {u4.x, u4.y, u4.z, u4.w};
            #pragma unroll
            for (int e = 0; e < 4; e++) {
                const unsigned u = uu[e];
                const unsigned d = u >> 20;
                if (d > bin12) sHi += __uint_as_float(u);
                const bool m = (d == bin12);
                const unsigned mk = __ballot_sync(0xffffffffu, m);
                if (mk) {
                    const int ldr = __ffs(mk) - 1;
                    int base = 0;
                    if (lane == ldr) base = atomicAdd(&g_candcnt[b], __popc(mk));
                    base = __shfl_sync(0xffffffffu, base, ldr);
                    if (m) g_cand[(size_t)b * NP + base +
                                  __popc(mk & ((1u << lane) - 1))] = __uint_as_float(u);
                }
            }
        }
        #pragma unroll
        for (int o = 16; o; o >>= 1) sHi += __shfl_xor_sync(0xffffffffu, sHi, o);
        __shared__ float wsf8[8];
        if (lane == 0) wsf8[wid] = sHi;
        __syncthreads();
        if (tid == 0) {
            float t = 0.f;
            #pragma unroll
            for (int i = 0; i < 8; i++) t += wsf8[i];
            atomicAdd(&g_sumHi[b], (double)t);
        }
    }

    // ---- per-batch done counter: last block resolves candidates ----
    __shared__ int s_plast;
    if (tid == 0) {
        __threadfence();
        s_plast = (atomicAdd(&g_pdone[b], 1) == PBLK - 1) ? 1 : 0;
    }
    __syncthreads();

    if (s_plast) {
        __threadfence();
        if (k > 0) {
            const int krem  = s_krem;
            const int bin12 = s_bin12;
            const int ncand = g_candcnt[b];
            const float* __restrict__ cv = g_cand + (size_t)b * NP;

            for (int i = tid; i < 4096; i += PTPB) { hist[i] = 0; fsum[i] = 0.f; }
            __syncthreads();

            // pass 1: bits[19:8] over candidates
            for (int i = tid; i < ncand; i += PTPB) {
                const unsigned u = __float_as_uint(cv[i]);
                const int bb = (u >> 8) & 4095;
                atomicAdd(&hist[bb], 1);
                atomicAdd(&fsum[bb], __uint_as_float(u));
            }
            __syncthreads();

            // find binA (per-thread 16-bin sums + serial walk)
            int part = 0;
            #pragma unroll
            for (int j = 0; j < 16; j++) part += hist[tid * 16 + j];
            ts[tid] = part;
            __syncthreads();
            if (tid == 0) {
                int kr = krem, g = PTPB - 1;
                for (;;) { const int c = ts[g]; if (c >= kr) break; kr -= c; g--; }
                int j = 15;
                for (;;) { const int c = hist[g * 16 + j]; if (c >= kr) break; kr -= c; j--; }
                s_binA = g * 16 + j; s_krem2 = kr;
            }
            __syncthreads();
            const int binA = s_binA;

            // suffix cnt/sum over bins > binA
            int cA = 0; float sA = 0.f;
            for (int i = tid; i < 4096; i += PTPB)
                if (i > binA) { cA += hist[i]; sA += fsum[i]; }
            #pragma unroll
            for (int o = 16; o; o >>= 1) {
                cA += __shfl_xor_sync(0xffffffffu, cA, o);
                sA += __shfl_xor_sync(0xffffffffu, sA, o);
            }
            __shared__ int wc[8]; __shared__ float wsf[8];
            if (lane == 0) { wc[wid] = cA; wsf[wid] = sA; }
            __syncthreads();
            int cntA = 0; float sumA = 0.f;
            #pragma unroll
            for (int i = 0; i < 8; i++) { cntA += wc[i]; sumA += wsf[i]; }
            __syncthreads();

            // pass 2: bits[7:0] for mid == binA
            if (tid < 256) { hist[tid] = 0; fsum[tid] = 0.f; }
            __syncthreads();
            for (int i = tid; i < ncand; i += PTPB) {
                const unsigned u = __float_as_uint(cv[i]);
                if ((int)((u >> 8) & 4095) == binA) {
                    atomicAdd(&hist[u & 255], 1);
                    atomicAdd(&fsum[u & 255], __uint_as_float(u));
                }
            }
            __syncthreads();

            // find binB (256 bins: 8 warps scan)
            if (wid < 8) {
                int v = hist[wid * 32 + lane];
                #pragma unroll
                for (int o = 16; o; o >>= 1) v += __shfl_xor_sync(0xffffffffu, v, o);
                if (lane == 0) ts[wid] = v;
            }
            __syncthreads();
            if (tid == 0) {
                int kr = s_krem2, g = 7;
                for (;;) { if (ts[g] >= kr) break; kr -= ts[g]; g--; }
                int j = 31;
                for (;;) { const int c = hist[g * 32 + j]; if (c >= kr) break; kr -= c; j--; }
                s_binB = g * 32 + j;
            }
            __syncthreads();
            const int binB = s_binB;

            int cB = 0; float sB = 0.f;
            if (tid < 256 && tid > binB) { cB = hist[tid]; sB = fsum[tid]; }
            #pragma unroll
            for (int o = 16; o; o >>= 1) {
                cB += __shfl_xor_sync(0xffffffffu, cB, o);
                sB += __shfl_xor_sync(0xffffffffu, sB, o);
            }
            if (lane == 0) { wc[wid] = cB; wsf[wid] = sB; }
            __syncthreads();

            if (tid == 0) {
                int cntB = 0; float sumB = 0.f;
                #pragma unroll
                for (int i = 0; i < 8; i++) { cntB += wc[i]; sumB += wsf[i]; }
                const unsigned T = ((unsigned)bin12 << 20) | ((unsigned)binA << 8) | (unsigned)binB;
                const double Tf = (double)__uint_as_float(T);
                const int    cntTot = (k - krem) + cntA + cntB;
                const double sumTot = g_sumHi[b] + (double)sumA + (double)sumB;
                atomicAdd(&g_conf_neg, sumTot + (double)(k - cntTot) * Tf);
            }
            __syncthreads();
        }
        // per-batch reset for next graph replay
        int* gh = g_hist12 + (b << 12);
        for (int i = tid; i < 4096; i += PTPB) gh[i] = 0;
        if (tid == 0) { g_candcnt[b] = 0; g_pdone[b] = 0; g_sumHi[b] = 0.0; }
    }

    // ---- global done counter: last of all 256 blocks finalizes + resets ----
    __shared__ int s_last;
    if (tid == 0) {
        __threadfence();
        s_last = (atomicAdd(&g_done, 1u) == (unsigned)(PGRID - 1)) ? 1 : 0;
    }
    __syncthreads();
    if (!s_last) return;
    __threadfence();

    __shared__ double fll[8], fce[8];
    double a = 0.0, c = 0.0;
    #pragma unroll
    for (int j = 0; j < NWSLOT / PTPB; j++) {
        a += g_part_lossl[tid + j * PTPB];
        c += g_part_cepos[tid + j * PTPB];
    }
    #pragma unroll
    for (int o = 16; o; o >>= 1) {
        a += __shfl_xor_sync(0xffffffffu, a, o);
        c += __shfl_xor_sync(0xffffffffu, c, o);
    }
    if (lane == 0) { fll[wid] = a; fce[wid] = c; }
    __syncthreads();
    if (tid == 0) {
        double ll = 0.0, ce = 0.0;
        #pragma unroll
        for (int i = 0; i < 8; i++) { ll += fll[i]; ce += fce[i]; }
        int N = 0;
        for (int i = 0; i < NB; i++) N += g_numpos[i];
        const double Nd = (double)N;
        out[0] = (float)(ll / Nd);
        out[1] = (float)((ce + g_conf_neg) / Nd);
        g_conf_neg = 0.0; g_done = 0u;
    }
    if (tid < NB) g_numpos[tid] = 0;
}

extern "C" void kernel_launch(void* const* d_in, const int* in_sizes, int n_in,
                              void* d_out, int out_size) {
    const float* loc_t = nullptr;
    const float* loc_data = nullptr;
    const int*   conf_t = nullptr;
    const float* conf_data = nullptr;
    for (int i = 0; i < n_in; i++) {
        if (in_sizes[i] == NANCH * NC)      conf_data = (const float*)d_in[i];
        else if (in_sizes[i] == NANCH)      conf_t    = (const int*)d_in[i];
        else if (in_sizes[i] == NANCH * 4) {
            if (!loc_t) loc_t = (const float*)d_in[i];
            else        loc_data = (const float*)d_in[i];
        }
    }

    static bool attr_set = false;
    if (!attr_set) {
        cudaFuncSetAttribute(mb_main_kernel,
                             cudaFuncAttributePreferredSharedMemoryCarveout, 100);
        attr_set = true;
    }

    mb_main_kernel<<<GRID, TPB>>>(loc_t, loc_data, conf_t, conf_data);
    mb_post_kernel<<<PGRID, PTPB>>>((float*)d_out);
}

// round 9
// speedup vs baseline: 1.2164x; 1.1147x over previous
#include <cuda_runtime.h>
#include <cuda_bf16.h>

#define NB 32
#define NP 32768
#define NC 81
#define NANCH (NB * NP)
#define TPB 128
#define WARPS 4
#define ROWS 8                           // rows per tile (per warp)
#define NBUF 3
#define WTILES 32                        // tiles per warp -> 256 anchors/warp
#define APB (WARPS * ROWS * WTILES)      // 1024 anchors per block
#define GRID (NANCH / APB)               // 1024 blocks, 32 per batch
#define TILE_FLOATS (ROWS * NC)          // 648
#define TILE_BYTES (TILE_FLOATS * 4)     // 2592
#define TILE_F4 (TILE_FLOATS / 4)       // 162
#define WARP_SMEM (NBUF * TILE_FLOATS)   // 1944 floats per warp
#define NWSLOT (GRID * WARPS)            // 4096 per-warp partial slots
#define PBLK 8                           // post blocks per batch
#define PGRID (NB * PBLK)                // 256
#define PTPB 256

// -------- scratch (device globals; zero-initialized at module load) --------
__device__ float  g_lossc[NANCH];         // mining scores (0 for pos/ignored)
__device__ double g_part_lossl[NWSLOT];   // per-warp smooth-L1 partials (plain ST)
__device__ double g_part_cepos[NWSLOT];   // per-warp CE-over-positives partials
__device__ int    g_numpos[NB];           // per-batch positive counts
__device__ int    g_hist12[NB * 4096];    // per-batch 12-bit (bits[31:20]) histogram
__device__ int    g_histA[NB * 4096];     // per-batch bits[19:8] histogram (boundary bin)
__device__ float  g_fsumA[NB * 4096];     // per-batch bits[19:8] value sums
__device__ int    g_pdone[NB];            // per-batch post-block completion counters
__device__ double g_sumHi[NB];            // per-batch sum of values above boundary bin
__device__ double g_conf_neg;             // CE sum over mined negatives
__device__ unsigned g_done;               // global completion counter

__device__ __forceinline__ unsigned smem_u32(const void* p) {
    return (unsigned)__cvta_generic_to_shared(p);
}
__device__ __forceinline__ void cp16(unsigned dst, const void* src) {
    asm volatile("cp.async.ca.shared.global [%0], [%1], 16;\n" :: "r"(dst), "l"(src));
}
#define CP_COMMIT() asm volatile("cp.async.commit_group;\n" ::: "memory")
#define CP_WAIT1()  asm volatile("cp.async.wait_group 1;\n" ::: "memory")

// ============ main: per-warp cp.async pipelines (lean; unchanged from R8) ============
__global__ void __launch_bounds__(TPB, 7) mb_main_kernel(
    const float* __restrict__ loc_t, const float* __restrict__ loc_data,
    const int* __restrict__ conf_t, const float* __restrict__ conf_data)
{
    __shared__ float smem[WARPS * WARP_SMEM];   // 31104 B

    const int tid  = threadIdx.x;
    const int w    = tid >> 5;
    const int lane = tid & 31;
    const int q    = lane & 3;
    const int row  = lane >> 2;
    const size_t wbase = (size_t)blockIdx.x * APB + (size_t)w * (ROWS * WTILES);
    float* const wsm = smem + w * WARP_SMEM;
    const unsigned sbase = smem_u32(wsm);
    const int hbase = (blockIdx.x >> 5) << 12;   // batch * 4096

    auto stage = [&](int t, int buf) {
        const float4* __restrict__ src =
            (const float4*)(conf_data) + (((size_t)(wbase + (size_t)t * ROWS) * NC) >> 2);
        const unsigned dst = sbase + (unsigned)buf * TILE_BYTES;
        #pragma unroll
        for (int j = 0; j < 5; j++)
            cp16(dst + (unsigned)(lane + j * 32) * 16u, src + lane + j * 32);
        if (lane < TILE_F4 - 160)
            cp16(dst + (unsigned)(lane + 160) * 16u, src + lane + 160);
    };

    stage(0, 0); CP_COMMIT();
    stage(1, 1); CP_COMMIT();

    float ll = 0.f, ce = 0.f;
    int   np = 0;
    int   cbuf = 0, sbuf = 2;

    for (int t = 0; t < WTILES; t++) {
        CP_WAIT1();
        __syncwarp();
        if (t + 2 < WTILES) stage(t + 2, sbuf);
        CP_COMMIT();
        sbuf = (sbuf == NBUF - 1) ? 0 : sbuf + 1;

        const float* __restrict__ r = wsm + cbuf * TILE_FLOATS + row * NC;
        cbuf = (cbuf == NBUF - 1) ? 0 : cbuf + 1;

        float s0 = 0.f, s1 = 0.f, s2 = 0.f, s3 = 0.f;
        #pragma unroll
        for (int i = 0; i < 20; i += 4) {
            s0 += __expf(r[q * 20 + i]);
            s1 += __expf(r[q * 20 + i + 1]);
            s2 += __expf(r[q * 20 + i + 2]);
            s3 += __expf(r[q * 20 + i + 3]);
        }
        float s = (s0 + s1) + (s2 + s3);
        if (q == 3) s += __expf(r[80]);
        s += __shfl_xor_sync(0xffffffffu, s, 1);
        s += __shfl_xor_sync(0xffffffffu, s, 2);

        if (q == 0) {
            const size_t anchor = wbase + (size_t)t * ROWS + row;
            const int traw = __ldg(&conf_t[anchor]);
            const int tgt  = traw < 0 ? 0 : traw;
            const float val = __logf(s) - r[tgt];          // cross-entropy

            const float stv = (traw == 0) ? fmaxf(val, 0.f) : 0.f;
            g_lossc[anchor] = stv;

            // fused radix digit 1: 12-bit histogram (8 active lanes, warp-aggregated)
            const unsigned bin = __float_as_uint(stv) >> 20;
            const unsigned peers = __match_any_sync(0x11111111u, bin);
            if (lane == __ffs(peers) - 1)
                atomicAdd(&g_hist12[hbase + (int)bin], __popc(peers));

            if (traw > 0) {
                float4 a = ((const float4*)loc_data)[anchor];
                float4 bb = ((const float4*)loc_t)[anchor];
                float d0 = fabsf(a.x - bb.x), d1 = fabsf(a.y - bb.y);
                float d2 = fabsf(a.z - bb.z), d3 = fabsf(a.w - bb.w);
                float sl1;
                sl1  = (d0 < 1.f) ? 0.5f * d0 * d0 : d0 - 0.5f;
                sl1 += (d1 < 1.f) ? 0.5f * d1 * d1 : d1 - 0.5f;
                sl1 += (d2 < 1.f) ? 0.5f * d2 * d2 : d2 - 0.5f;
                sl1 += (d3 < 1.f) ? 0.5f * d3 * d3 : d3 - 0.5f;
                ll += sl1; ce += val; np++;
            }
        }
    }

    #pragma unroll
    for (int o = 16; o; o >>= 1) {
        ll += __shfl_xor_sync(0xffffffffu, ll, o);
        ce += __shfl_xor_sync(0xffffffffu, ce, o);
        np += __shfl_xor_sync(0xffffffffu, np, o);
    }
    if (lane == 0) {
        const int slot = blockIdx.x * WARPS + w;
        g_part_lossl[slot] = (double)ll;
        g_part_cepos[slot] = (double)ce;
        if (np) atomicAdd(&g_numpos[blockIdx.x >> 5], np);
    }
}

// ============ post: 1 data pass, parallel threshold finds, 24-bit resolution ============
__global__ void __launch_bounds__(PTPB) mb_post_kernel(float* __restrict__ out) {
    const int b     = blockIdx.x >> 3;
    const int slice = blockIdx.x & (PBLK - 1);
    const int tid = threadIdx.x, lane = tid & 31, wid = tid >> 5;

    __shared__ int   hist[4096];
    __shared__ float fsum[4096];
    __shared__ int   wtot[8];
    __shared__ int   s_bin12, s_krem, s_binA, s_krem2;

    const int np = g_numpos[b];
    const int k  = min(3 * np, NP - 1);

    // parallel "find bin with suffix-count crossing k" over 4096 chunked bins.
    // hist[] holds the bins (chunk layout: thread t owns bins [16t,16t+16)).
    auto find_bin = [&](int kk, int& out_bin, int& out_krem, int* sbin, int* skrem) {
        int part = 0;
        #pragma unroll
        for (int j = 0; j < 16; j++) part += hist[tid * 16 + j];
        // inclusive suffix within warp (sum of lanes >= lane)
        int s = part;
        #pragma unroll
        for (int o = 1; o < 32; o <<= 1) {
            const int v = __shfl_down_sync(0xffffffffu, s, o);
            if (lane + o < 32) s += v;
        }
        if (lane == 0) wtot[wid] = s;   // warp total
        __syncthreads();
        int hi = 0;
        #pragma unroll
        for (int i = 0; i < 8; i++) if (i > wid) hi += wtot[i];
        const int S_excl = (s - part) + hi;   // count in bins strictly above my chunk
        if (S_excl < kk && S_excl + part >= kk) {   // exactly one thread crosses
            int krem = kk - S_excl;
            int j = 15;
            for (;;) { const int c = hist[tid * 16 + j]; if (c >= krem) break; krem -= c; j--; }
            *sbin = tid * 16 + j; *skrem = krem;
        }
        __syncthreads();
        out_bin = *sbin; out_krem = *skrem;
    };

    if (k > 0) {
        // ---- phase 1: every block redundantly finds bin12 from L2-resident hist12 ----
        const int* __restrict__ gh = g_hist12 + (b << 12);
        #pragma unroll
        for (int j = 0; j < 16; j++) hist[tid * 16 + j] = __ldg(&gh[tid * 16 + j]);
        __syncthreads();
        int bin12i, krem;
        find_bin(k, bin12i, krem, &s_bin12, &s_krem);
        const unsigned bin12 = (unsigned)bin12i;

        // ---- phase 2: single slice scan -> sumHi + smem hist of bits[19:8] ----
        for (int i = tid; i < 4096; i += PTPB) { hist[i] = 0; fsum[i] = 0.f; }
        __syncthreads();

        const uint4* __restrict__ uv = (const uint4*)
            ((const unsigned*)g_lossc + (size_t)b * NP + slice * (NP / PBLK));
        float sHi = 0.f;
        #pragma unroll
        for (int j = 0; j < 4; j++) {
            const uint4 u4 = __ldg(&uv[tid + j * PTPB]);
            const unsigned uu[4] = {u4.x, u4.y, u4.z, u4.w};
            #pragma unroll
            for (int e = 0; e < 4; e++) {
                const unsigned u = uu[e];
                const unsigned d = u >> 20;
                if (d > bin12) sHi += __uint_as_float(u);
                else if (d == bin12) {
                    const int bb = (u >> 8) & 4095;
                    atomicAdd(&hist[bb], 1);
                    atomicAdd(&fsum[bb], __uint_as_float(u));
                }
            }
        }
        #pragma unroll
        for (int o = 16; o; o >>= 1) sHi += __shfl_xor_sync(0xffffffffu, sHi, o);
        __shared__ float wsf8[8];
        if (lane == 0) wsf8[wid] = sHi;
        __syncthreads();
        if (tid == 0) {
            float t = 0.f;
            #pragma unroll
            for (int i = 0; i < 8; i++) t += wsf8[i];
            atomicAdd(&g_sumHi[b], (double)t);
        }
        // sparse merge of boundary-bin histogram into per-batch global
        for (int i = tid; i < 4096; i += PTPB) {
            const int c = hist[i];
            if (c) {
                atomicAdd(&g_histA[(b << 12) + i], c);
                atomicAdd(&g_fsumA[(b << 12) + i], fsum[i]);
            }
        }
    }

    // ---- per-batch done counter: last block resolves (no further data passes) ----
    __shared__ int s_plast;
    if (tid == 0) {
        __threadfence();
        s_plast = (atomicAdd(&g_pdone[b], 1) == PBLK - 1) ? 1 : 0;
    }
    __syncthreads();

    if (s_plast) {
        __threadfence();
        if (k > 0) {
            const int krem = s_krem;
            const unsigned bin12 = (unsigned)s_bin12;
            int* __restrict__ gha = g_histA + (b << 12);
            float* __restrict__ gfa = g_fsumA + (b << 12);
            #pragma unroll
            for (int j = 0; j < 16; j++) {
                hist[tid * 16 + j] = gha[tid * 16 + j];
                fsum[tid * 16 + j] = gfa[tid * 16 + j];
            }
            __syncthreads();
            int binA, krem2;
            find_bin(krem, binA, krem2, &s_binA, &s_krem2);

            // suffix cnt/sum over bins > binA (parallel)
            int cA = 0; float sA = 0.f;
            for (int i = tid; i < 4096; i += PTPB)
                if (i > binA) { cA += hist[i]; sA += fsum[i]; }
            #pragma unroll
            for (int o = 16; o; o >>= 1) {
                cA += __shfl_xor_sync(0xffffffffu, cA, o);
                sA += __shfl_xor_sync(0xffffffffu, sA, o);
            }
            __shared__ int wc[8]; __shared__ float wsf[8];
            if (lane == 0) { wc[wid] = cA; wsf[wid] = sA; }
            __syncthreads();
            if (tid == 0) {
                int cnt = 0; float sm = 0.f;
                #pragma unroll
                for (int i = 0; i < 8; i++) { cnt += wc[i]; sm += wsf[i]; }
                // 24-bit threshold, midpoint of the low byte (residual < 1e-7 rel on sum)
                const unsigned T = (bin12 << 20) | ((unsigned)binA << 8) | 0x80u;
                const double Tf = (double)__uint_as_float(T);
                const double sumTot = g_sumHi[b] + (double)sm;
                const int    cntTot = (k - krem) + cnt;
                atomicAdd(&g_conf_neg, sumTot + (double)(k - cntTot) * Tf);
            }
            __syncthreads();
        }
        // per-batch reset for next graph replay
        int* gh  = g_hist12 + (b << 12);
        int* gha = g_histA + (b << 12);
        float* gfa = g_fsumA + (b << 12);
        for (int i = tid; i < 4096; i += PTPB) { gh[i] = 0; gha[i] = 0; gfa[i] = 0.f; }
        if (tid == 0) { g_pdone[b] = 0; g_sumHi[b] = 0.0; }
    }

    // ---- global done counter: last of all blocks finalizes + resets ----
    __shared__ int s_last;
    if (tid == 0) {
        __threadfence();
        s_last = (atomicAdd(&g_done, 1u) == (unsigned)(PGRID - 1)) ? 1 : 0;
    }
    __syncthreads();
    if (!s_last) return;
    __threadfence();

    __shared__ double fll[8], fce[8];
    double a = 0.0, c = 0.0;
    #pragma unroll
    for (int j = 0; j < NWSLOT / PTPB; j++) {
        a += g_part_lossl[tid + j * PTPB];
        c += g_part_cepos[tid + j * PTPB];
    }
    #pragma unroll
    for (int o = 16; o; o >>= 1) {
        a += __shfl_xor_sync(0xffffffffu, a, o);
        c += __shfl_xor_sync(0xffffffffu, c, o);
    }
    if (lane == 0) { fll[wid] = a; fce[wid] = c; }
    __syncthreads();
    if (tid == 0) {
        double ll = 0.0, ce = 0.0;
        #pragma unroll
        for (int i = 0; i < 8; i++) { ll += fll[i]; ce += fce[i]; }
        int N = 0;
        for (int i = 0; i < NB; i++) N += g_numpos[i];
        const double Nd = (double)N;
        out[0] = (float)(ll / Nd);
        out[1] = (float)((ce + g_conf_neg) / Nd);
        g_conf_neg = 0.0; g_done = 0u;
    }
    if (tid < NB) g_numpos[tid] = 0;
}

extern "C" void kernel_launch(void* const* d_in, const int* in_sizes, int n_in,
                              void* d_out, int out_size) {
    const float* loc_t = nullptr;
    const float* loc_data = nullptr;
    const int*   conf_t = nullptr;
    const float* conf_data = nullptr;
    for (int i = 0; i < n_in; i++) {
        if (in_sizes[i] == NANCH * NC)      conf_data = (const float*)d_in[i];
        else if (in_sizes[i] == NANCH)      conf_t    = (const int*)d_in[i];
        else if (in_sizes[i] == NANCH * 4) {
            if (!loc_t) loc_t = (const float*)d_in[i];
            else        loc_data = (const float*)d_in[i];
        }
    }

    static bool attr_set = false;
    if (!attr_set) {
        cudaFuncSetAttribute(mb_main_kernel,
                             cudaFuncAttributePreferredSharedMemoryCarveout, 100);
        attr_set = true;
    }

    mb_main_kernel<<<GRID, TPB>>>(loc_t, loc_data, conf_t, conf_data);
    mb_post_kernel<<<PGRID, PTPB>>>((float*)d_out);
}

// round 10
// speedup vs baseline: 1.3031x; 1.0713x over previous
#include <cuda_runtime.h>
#include <cuda_bf16.h>

#define NB 32
#define NP 32768
#define NC 81
#define NANCH (NB * NP)
#define TPB 128
#define WARPS 4
#define ROWS 8                           // rows per tile (per warp)
#define NBUF 3
#define WTILES 32                        // tiles per warp -> 256 anchors/warp
#define APB (WARPS * ROWS * WTILES)      // 1024 anchors per block
#define GRID (NANCH / APB)               // 1024 blocks, 32 per batch
#define TILE_FLOATS (ROWS * NC)          // 648
#define TILE_BYTES (TILE_FLOATS * 4)     // 2592
#define TILE_F4 (TILE_FLOATS / 4)        // 162
#define WARP_SMEM (NBUF * TILE_FLOATS)   // 1944 floats per warp
#define NWSLOT (GRID * WARPS)            // 4096 per-warp partial slots
#define PTPB 1024

// -------- scratch (device globals; zero-initialized at module load) --------
__device__ float  g_lossc[NANCH];         // mining scores (0 for pos/ignored)
__device__ double g_part_lossl[NWSLOT];   // per-warp smooth-L1 partials (plain ST)
__device__ double g_part_cepos[NWSLOT];   // per-warp CE-over-positives partials
__device__ int    g_numpos[NB];           // per-batch positive counts
__device__ int    g_hist12[NB * 4096];    // per-batch 12-bit (bits[31:20]) histogram
__device__ double g_conf_neg;             // CE sum over mined negatives
__device__ unsigned g_done;               // global completion counter

__device__ __forceinline__ unsigned smem_u32(const void* p) {
    return (unsigned)__cvta_generic_to_shared(p);
}
__device__ __forceinline__ void cp16(unsigned dst, const void* src) {
    asm volatile("cp.async.ca.shared.global [%0], [%1], 16;\n" :: "r"(dst), "l"(src));
}
#define CP_COMMIT() asm volatile("cp.async.commit_group;\n" ::: "memory")
#define CP_WAIT1()  asm volatile("cp.async.wait_group 1;\n" ::: "memory")

// ============ main: per-warp cp.async pipelines (unchanged — stable ~81us) ============
__global__ void __launch_bounds__(TPB, 7) mb_main_kernel(
    const float* __restrict__ loc_t, const float* __restrict__ loc_data,
    const int* __restrict__ conf_t, const float* __restrict__ conf_data)
{
    __shared__ float smem[WARPS * WARP_SMEM];   // 31104 B

    const int tid  = threadIdx.x;
    const int w    = tid >> 5;
    const int lane = tid & 31;
    const int q    = lane & 3;
    const int row  = lane >> 2;
    const size_t wbase = (size_t)blockIdx.x * APB + (size_t)w * (ROWS * WTILES);
    float* const wsm = smem + w * WARP_SMEM;
    const unsigned sbase = smem_u32(wsm);
    const int hbase = (blockIdx.x >> 5) << 12;   // batch * 4096

    auto stage = [&](int t, int buf) {
        const float4* __restrict__ src =
            (const float4*)(conf_data) + (((size_t)(wbase + (size_t)t * ROWS) * NC) >> 2);
        const unsigned dst = sbase + (unsigned)buf * TILE_BYTES;
        #pragma unroll
        for (int j = 0; j < 5; j++)
            cp16(dst + (unsigned)(lane + j * 32) * 16u, src + lane + j * 32);
        if (lane < TILE_F4 - 160)
            cp16(dst + (unsigned)(lane + 160) * 16u, src + lane + 160);
    };

    stage(0, 0); CP_COMMIT();
    stage(1, 1); CP_COMMIT();

    float ll = 0.f, ce = 0.f;
    int   np = 0;
    int   cbuf = 0, sbuf = 2;

    for (int t = 0; t < WTILES; t++) {
        CP_WAIT1();
        __syncwarp();
        if (t + 2 < WTILES) stage(t + 2, sbuf);
        CP_COMMIT();
        sbuf = (sbuf == NBUF - 1) ? 0 : sbuf + 1;

        const float* __restrict__ r = wsm + cbuf * TILE_FLOATS + row * NC;
        cbuf = (cbuf == NBUF - 1) ? 0 : cbuf + 1;

        float s0 = 0.f, s1 = 0.f, s2 = 0.f, s3 = 0.f;
        #pragma unroll
        for (int i = 0; i < 20; i += 4) {
            s0 += __expf(r[q * 20 + i]);
            s1 += __expf(r[q * 20 + i + 1]);
            s2 += __expf(r[q * 20 + i + 2]);
            s3 += __expf(r[q * 20 + i + 3]);
        }
        float s = (s0 + s1) + (s2 + s3);
        if (q == 3) s += __expf(r[80]);
        s += __shfl_xor_sync(0xffffffffu, s, 1);
        s += __shfl_xor_sync(0xffffffffu, s, 2);

        if (q == 0) {
            const size_t anchor = wbase + (size_t)t * ROWS + row;
            const int traw = __ldg(&conf_t[anchor]);
            const int tgt  = traw < 0 ? 0 : traw;
            const float val = __logf(s) - r[tgt];          // cross-entropy

            const float stv = (traw == 0) ? fmaxf(val, 0.f) : 0.f;
            g_lossc[anchor] = stv;

            // fused radix digit 1: 12-bit histogram (8 active lanes, warp-aggregated)
            const unsigned bin = __float_as_uint(stv) >> 20;
            const unsigned peers = __match_any_sync(0x11111111u, bin);
            if (lane == __ffs(peers) - 1)
                atomicAdd(&g_hist12[hbase + (int)bin], __popc(peers));

            if (traw > 0) {
                float4 a = ((const float4*)loc_data)[anchor];
                float4 bb = ((const float4*)loc_t)[anchor];
                float d0 = fabsf(a.x - bb.x), d1 = fabsf(a.y - bb.y);
                float d2 = fabsf(a.z - bb.z), d3 = fabsf(a.w - bb.w);
                float sl1;
                sl1  = (d0 < 1.f) ? 0.5f * d0 * d0 : d0 - 0.5f;
                sl1 += (d1 < 1.f) ? 0.5f * d1 * d1 : d1 - 0.5f;
                sl1 += (d2 < 1.f) ? 0.5f * d2 * d2 : d2 - 0.5f;
                sl1 += (d3 < 1.f) ? 0.5f * d3 * d3 : d3 - 0.5f;
                ll += sl1; ce += val; np++;
            }
        }
    }

    #pragma unroll
    for (int o = 16; o; o >>= 1) {
        ll += __shfl_xor_sync(0xffffffffu, ll, o);
        ce += __shfl_xor_sync(0xffffffffu, ce, o);
        np += __shfl_xor_sync(0xffffffffu, np, o);
    }
    if (lane == 0) {
        const int slot = blockIdx.x * WARPS + w;
        g_part_lossl[slot] = (double)ll;
        g_part_cepos[slot] = (double)ce;
        if (np) atomicAdd(&g_numpos[blockIdx.x >> 5], np);
    }
}

// ============ post: ONE block per batch; single pass; fully in-block resolve ============
__global__ void __launch_bounds__(PTPB) mb_post_kernel(float* __restrict__ out) {
    const int b = blockIdx.x;
    const int tid = threadIdx.x, lane = tid & 31, wid = tid >> 5;

    __shared__ int   hist[4096];
    __shared__ float fsum[4096];
    __shared__ int   wtot[32];
    __shared__ float wsf[32];
    __shared__ int   s_bin, s_krem;

    // parallel "find bin where descending cumulative count crosses kk".
    // chunk layout: thread t owns bins [4t, 4t+4).
    auto find_bin = [&](int kk, int& out_bin, int& out_krem) {
        int part = 0;
        #pragma unroll
        for (int j = 0; j < 4; j++) part += hist[tid * 4 + j];
        int s = part;                     // inclusive suffix within warp
        #pragma unroll
        for (int o = 1; o < 32; o <<= 1) {
            const int v = __shfl_down_sync(0xffffffffu, s, o);
            if (lane + o < 32) s += v;
        }
        if (lane == 0) wtot[wid] = s;
        __syncthreads();
        int hi = 0;
        #pragma unroll
        for (int i = 0; i < 32; i++) if (i > wid) hi += wtot[i];
        const int S_excl = (s - part) + hi;        // count in bins strictly above my chunk
        if (S_excl < kk && S_excl + part >= kk) {  // exactly one thread crosses
            int krem = kk - S_excl;
            int j = 3;
            for (;;) { const int c = hist[tid * 4 + j]; if (c >= krem) break; krem -= c; j--; }
            s_bin = tid * 4 + j; s_krem = krem;
        }
        __syncthreads();
        out_bin = s_bin; out_krem = s_krem;
    };

    const int np = g_numpos[b];
    const int k  = min(3 * np, NP - 1);
    int* __restrict__ gh = g_hist12 + (b << 12);

    if (k > 0) {
        // ---- phase 1: find bin12 from this batch's fused histogram ----
        #pragma unroll
        for (int j = 0; j < 4; j++) hist[tid * 4 + j] = __ldg(&gh[tid * 4 + j]);
        __syncthreads();
        int bin12i, krem;
        find_bin(k, bin12i, krem);
        const unsigned bin12 = (unsigned)bin12i;
        __syncthreads();

        // ---- phase 2: single full-batch scan -> sumHi + smem hist of bits[19:8] ----
        #pragma unroll
        for (int j = 0; j < 4; j++) { hist[tid * 4 + j] = 0; fsum[tid * 4 + j] = 0.f; }
        __syncthreads();

        const uint4* __restrict__ uv =
            (const uint4*)((const unsigned*)g_lossc + (size_t)b * NP);
        float sHi = 0.f;
        #pragma unroll
        for (int j = 0; j < 8; j++) {
            const uint4 u4 = __ldg(&uv[tid + j * PTPB]);
            const unsigned uu[4] = {u4.x, u4.y, u4.z, u4.w};
            #pragma unroll
            for (int e = 0; e < 4; e++) {
                const unsigned u = uu[e];
                const unsigned d = u >> 20;
                if (d > bin12) sHi += __uint_as_float(u);
                else if (d == bin12) {
                    const int bb = (u >> 8) & 4095;
                    atomicAdd(&hist[bb], 1);
                    atomicAdd(&fsum[bb], __uint_as_float(u));
                }
            }
        }
        #pragma unroll
        for (int o = 16; o; o >>= 1) sHi += __shfl_xor_sync(0xffffffffu, sHi, o);
        if (lane == 0) wsf[wid] = sHi;
        __syncthreads();

        // ---- phase 3: find binA; suffix cnt/sum; finalize threshold sum ----
        int binA, krem2;
        find_bin(krem, binA, krem2);

        int cA = 0; float sA = 0.f;
        #pragma unroll
        for (int j = 0; j < 4; j++) {
            const int i = tid * 4 + j;
            if (i > binA) { cA += hist[i]; sA += fsum[i]; }
        }
        #pragma unroll
        for (int o = 16; o; o >>= 1) {
            cA += __shfl_xor_sync(0xffffffffu, cA, o);
            sA += __shfl_xor_sync(0xffffffffu, sA, o);
        }
        __shared__ int wc2[32]; __shared__ float ws2[32];
        if (lane == 0) { wc2[wid] = cA; ws2[wid] = sA; }
        __syncthreads();
        if (tid == 0) {
            int cnt = 0; float sm = 0.f; float shi = 0.f;
            #pragma unroll
            for (int i = 0; i < 32; i++) { cnt += wc2[i]; sm += ws2[i]; shi += wsf[i]; }
            // 24-bit threshold, midpoint of low byte (residual < 1e-7 rel on sum)
            const unsigned T = (bin12 << 20) | ((unsigned)binA << 8) | 0x80u;
            const double Tf = (double)__uint_as_float(T);
            const int    cntTot = (k - krem) + cnt;
            atomicAdd(&g_conf_neg, (double)shi + (double)sm + (double)(k - cntTot) * Tf);
        }
        __syncthreads();
    }

    // reset this batch's fused histogram for the next graph replay
    #pragma unroll
    for (int j = 0; j < 4; j++) gh[tid * 4 + j] = 0;

    // ---- global done counter: last of 32 blocks finalizes + resets ----
    __shared__ int s_last;
    if (tid == 0) {
        __threadfence();
        s_last = (atomicAdd(&g_done, 1u) == (unsigned)(NB - 1)) ? 1 : 0;
    }
    __syncthreads();
    if (!s_last) return;
    __threadfence();

    __shared__ double fll[32], fce[32];
    double a = 0.0, c = 0.0;
    #pragma unroll
    for (int j = 0; j < NWSLOT / PTPB; j++) {
        a += g_part_lossl[tid + j * PTPB];
        c += g_part_cepos[tid + j * PTPB];
    }
    #pragma unroll
    for (int o = 16; o; o >>= 1) {
        a += __shfl_xor_sync(0xffffffffu, a, o);
        c += __shfl_xor_sync(0xffffffffu, c, o);
    }
    if (lane == 0) { fll[wid] = a; fce[wid] = c; }
    __syncthreads();
    if (tid == 0) {
        double ll = 0.0, ce = 0.0;
        #pragma unroll
        for (int i = 0; i < 32; i++) { ll += fll[i]; ce += fce[i]; }
        int N = 0;
        for (int i = 0; i < NB; i++) N += g_numpos[i];
        const double Nd = (double)N;
        out[0] = (float)(ll / Nd);
        out[1] = (float)((ce + g_conf_neg) / Nd);
        g_conf_neg = 0.0; g_done = 0u;
    }
    if (tid < NB) g_numpos[tid] = 0;
}

extern "C" void kernel_launch(void* const* d_in, const int* in_sizes, int n_in,
                              void* d_out, int out_size) {
    const float* loc_t = nullptr;
    const float* loc_data = nullptr;
    const int*   conf_t = nullptr;
    const float* conf_data = nullptr;
    for (int i = 0; i < n_in; i++) {
        if (in_sizes[i] == NANCH * NC)      conf_data = (const float*)d_in[i];
        else if (in_sizes[i] == NANCH)      conf_t    = (const int*)d_in[i];
        else if (in_sizes[i] == NANCH * 4) {
            if (!loc_t) loc_t = (const float*)d_in[i];
            else        loc_data = (const float*)d_in[i];
        }
    }

    static bool attr_set = false;
    if (!attr_set) {
        cudaFuncSetAttribute(mb_main_kernel,
                             cudaFuncAttributePreferredSharedMemoryCarveout, 100);
        attr_set = true;
    }

    mb_main_kernel<<<GRID, TPB>>>(loc_t, loc_data, conf_t, conf_data);
    mb_post_kernel<<<NB, PTPB>>>((float*)d_out);
}